// round 7
// baseline (speedup 1.0000x reference)
#include <cuda_runtime.h>
#include <stdint.h>
#include <math.h>

#define BSZ 2
#define SEQ 2048
#define EMB 768
#define NH  12
#define HD  64
#define BH  (BSZ*NH)     /* 24  */
#define MTOK (BSZ*SEQ)   /* 4096 */

// ---------------------------------------------------------------------------
// Scratch
// ---------------------------------------------------------------------------
__device__ float g_Q[BH * SEQ * HD];
__device__ float g_K[BH * SEQ * HD];
__device__ float g_V[BH * SEQ * HD];
__device__ float g_O[MTOK * EMB];          // attention out, tf32-rounded
__device__ float g_X[MTOK * EMB];          // tf32-rounded hidden states
__device__ float g_W4[4 * EMB * EMB];      // tf32-rounded Wq,Wk,Wv,Wo
__device__ int   g_mask_nz;

// ---------------------------------------------------------------------------
// Mask scan
// ---------------------------------------------------------------------------
__global__ void reset_flag_kernel() { g_mask_nz = 0; }

__global__ void scan_mask_kernel(const float* __restrict__ mask, int n4) {
    int i = blockIdx.x * blockDim.x + threadIdx.x;
    int stride = gridDim.x * blockDim.x;
    int nz = 0;
    for (; i < n4; i += stride) {
        float4 v = ((const float4*)mask)[i];
        nz |= (v.x != 0.f) | (v.y != 0.f) | (v.z != 0.f) | (v.w != 0.f);
    }
    if (__syncthreads_or(nz)) {
        if (threadIdx.x == 0) atomicOr(&g_mask_nz, 1);
    }
}

// ---------------------------------------------------------------------------
// tf32 / cp.async helpers
// ---------------------------------------------------------------------------
__device__ __forceinline__ unsigned cvt_tf32(float x) {
    unsigned r;
    asm("cvt.rna.tf32.f32 %0, %1;" : "=r"(r) : "f"(x));
    return r;
}
__device__ __forceinline__ float cvt_tf32_f(float x) {
    return __uint_as_float(cvt_tf32(x));
}

__device__ __forceinline__ void mma_tf32(float c[4], const unsigned a[4],
                                         unsigned b0, unsigned b1) {
    asm("mma.sync.aligned.m16n8k8.row.col.f32.tf32.tf32.f32 "
        "{%0,%1,%2,%3},{%4,%5,%6,%7},{%8,%9},{%0,%1,%2,%3};"
        : "+f"(c[0]), "+f"(c[1]), "+f"(c[2]), "+f"(c[3])
        : "r"(a[0]), "r"(a[1]), "r"(a[2]), "r"(a[3]), "r"(b0), "r"(b1));
}

__device__ __forceinline__ void cp_async16(unsigned saddr, const void* gptr) {
    asm volatile("cp.async.cg.shared.global [%0], [%1], 16;"
                 :: "r"(saddr), "l"(gptr));
}
__device__ __forceinline__ void cp_commit() {
    asm volatile("cp.async.commit_group;");
}
template <int N>
__device__ __forceinline__ void cp_wait() {
    asm volatile("cp.async.wait_group %0;" :: "n"(N));
}

// ---------------------------------------------------------------------------
// Pre-round pass: X and the 4 weight matrices -> tf32 (rna), into scratch.
// After this, GEMM operands can be cp.async'd raw (mma truncation is exact
// on pre-rounded values) with numerics identical to cvt-at-load.
// ---------------------------------------------------------------------------
__global__ void round_inputs_kernel(
    const float* __restrict__ X,
    const float* __restrict__ Wq, const float* __restrict__ Wk,
    const float* __restrict__ Wv, const float* __restrict__ Wo)
{
    int i = blockIdx.x * blockDim.x + threadIdx.x;
    int stride = gridDim.x * blockDim.x;
    const int NX = MTOK * EMB / 4;
    const int NW = EMB * EMB / 4;
    for (int k = i; k < NX; k += stride) {
        float4 v = ((const float4*)X)[k];
        v.x = cvt_tf32_f(v.x); v.y = cvt_tf32_f(v.y);
        v.z = cvt_tf32_f(v.z); v.w = cvt_tf32_f(v.w);
        ((float4*)g_X)[k] = v;
    }
    const float* Ws[4] = {Wq, Wk, Wv, Wo};
#pragma unroll
    for (int s = 0; s < 4; s++) {
        float4* dst = (float4*)(g_W4 + (size_t)s * EMB * EMB);
        const float4* src = (const float4*)Ws[s];
        for (int k = i; k < NW; k += stride) {
            float4 v = src[k];
            v.x = cvt_tf32_f(v.x); v.y = cvt_tf32_f(v.y);
            v.z = cvt_tf32_f(v.z); v.w = cvt_tf32_f(v.w);
            dst[k] = v;
        }
    }
}

// ---------------------------------------------------------------------------
// Pipelined tf32 GEMM core: C(128x128) = A(128xEMB) @ W^T(128xEMB).
// Inputs must be pre-rounded to tf32. 256 thr = 8 warps (4m x 2n),
// warp tile 32x64. BK=32, 2-stage cp.async double buffer.
// Direct smem layout, row stride 36: fragment bank = (4g+m+8t)%32 ->
// conflict-free scalar LDS.32 for both A and B fragments.
// ---------------------------------------------------------------------------
#define DSW 36
#define GST (128 * DSW)                 /* floats per operand per stage */
#define GEMM_SMEM (4 * GST * 4)         /* bytes: 2 stages x (A+B) */

struct GemmAcc { float a[2][8][4]; };

__device__ __forceinline__ void gemm_pipe_core(
    const float* __restrict__ A, const float* __restrict__ W,
    int bm, int bn, GemmAcc& acc, float* sm)
{
    int tid = threadIdx.x;
    int lane = tid & 31;
    int wid = tid >> 5;
    int g = lane >> 2, m = lane & 3;
    int wm = wid & 3, wn = wid >> 2;

#pragma unroll
    for (int im = 0; im < 2; im++)
#pragma unroll
        for (int jn = 0; jn < 8; jn++)
#pragma unroll
            for (int i = 0; i < 4; i++) acc.a[im][jn][i] = 0.f;

    unsigned sbase = (unsigned)__cvta_generic_to_shared(sm);
    int rowc = tid >> 1;            // 0..127
    int cOff = (tid & 1) * 4;       // chunk base (16B units): 0 or 4
    const float* agp = A + (size_t)(bm + rowc) * EMB + cOff * 4;
    const float* bgp = W + (size_t)(bn + rowc) * EMB + cOff * 4;
    unsigned soff = (unsigned)(rowc * DSW + cOff * 4) * 4;

    auto issue = [&](int k0, int st) {
        unsigned as = sbase + (unsigned)st * (2 * GST * 4);
        unsigned bs = as + GST * 4;
#pragma unroll
        for (int u = 0; u < 4; u++) {
            cp_async16(as + soff + u * 16, agp + k0 + u * 4);
            cp_async16(bs + soff + u * 16, bgp + k0 + u * 4);
        }
        cp_commit();
    };

    issue(0, 0);
    const int NIT = EMB / 32;
    for (int it = 0; it < NIT; it++) {
        if (it + 1 < NIT) { issue((it + 1) * 32, (it + 1) & 1); cp_wait<1>(); }
        else              { cp_wait<0>(); }
        __syncthreads();

        const float* As = sm + (it & 1) * 2 * GST;
        const float* Bs = As + GST;

#pragma unroll
        for (int t = 0; t < 4; t++) {
            unsigned af[2][4];
#pragma unroll
            for (int im = 0; im < 2; im++) {
                const float* ab = As + (wm * 32 + im * 16 + g) * DSW + 8 * t + m;
                af[im][0] = __float_as_uint(ab[0]);
                af[im][2] = __float_as_uint(ab[4]);
                af[im][1] = __float_as_uint(ab[8 * DSW]);
                af[im][3] = __float_as_uint(ab[8 * DSW + 4]);
            }
#pragma unroll
            for (int jn = 0; jn < 8; jn++) {
                const float* bb = Bs + (wn * 64 + jn * 8 + g) * DSW + 8 * t + m;
                unsigned b0 = __float_as_uint(bb[0]);
                unsigned b1 = __float_as_uint(bb[4]);
                mma_tf32(acc.a[0][jn], af[0], b0, b1);
                mma_tf32(acc.a[1][jn], af[1], b0, b1);
            }
        }
        __syncthreads();
    }
}

// ---------------------------------------------------------------------------
// QKV projection: grid (18, 32). Writes [bh][s][d], tf32-rounded (Q scaled).
// ---------------------------------------------------------------------------
__global__ void __launch_bounds__(256) qkv_gemm_pipe_kernel(
    const float* __restrict__ bq, const float* __restrict__ bk,
    const float* __restrict__ bv)
{
    extern __shared__ __align__(16) float sm[];

    int bx  = blockIdx.x;
    int seg = bx / 6;
    int nb  = bx % 6;
    int bm  = blockIdx.y * 128;

    const float* W    = g_W4 + (size_t)seg * EMB * EMB;
    const float* bias = (seg == 0) ? bq : (seg == 1) ? bk : bv;
    float*       out  = (seg == 0) ? g_Q : (seg == 1) ? g_K : g_V;
    const float scale = (seg == 0) ? 0.125f : 1.0f;

    GemmAcc acc;
    gemm_pipe_core(g_X, W, bm, nb * 128, acc, sm);

    int lane = threadIdx.x & 31;
    int wid  = threadIdx.x >> 5;
    int g = lane >> 2, m = lane & 3;
    int wm = wid & 3, wn = wid >> 2;

#pragma unroll
    for (int im = 0; im < 2; im++) {
        int r0 = bm + wm * 32 + im * 16 + g;
#pragma unroll
        for (int jn = 0; jn < 8; jn++) {
            int nloc = nb * 128 + wn * 64 + jn * 8 + 2 * m;
            int h = nloc >> 6, d = nloc & 63;
            float b0v = bias[nloc], b1v = bias[nloc + 1];
            int b = r0 >> 11, s0 = r0 & 2047;
            float* o0 = out + ((size_t)((b * NH + h) * SEQ + s0)) * HD + d;
            float* o1 = o0 + (size_t)8 * HD;
            *(float2*)o0 = make_float2(cvt_tf32_f((acc.a[im][jn][0] + b0v) * scale),
                                       cvt_tf32_f((acc.a[im][jn][1] + b1v) * scale));
            *(float2*)o1 = make_float2(cvt_tf32_f((acc.a[im][jn][2] + b0v) * scale),
                                       cvt_tf32_f((acc.a[im][jn][3] + b1v) * scale));
        }
    }
}

// ---------------------------------------------------------------------------
// Output projection: grid (6, 32). d_out = g_O @ Wo^T + bo (fp32 out).
// ---------------------------------------------------------------------------
__global__ void __launch_bounds__(256) oproj_gemm_pipe_kernel(
    const float* __restrict__ bias, float* __restrict__ C)
{
    extern __shared__ __align__(16) float sm[];

    int bn = blockIdx.x * 128;
    int bm = blockIdx.y * 128;

    GemmAcc acc;
    gemm_pipe_core(g_O, g_W4 + (size_t)3 * EMB * EMB, bm, bn, acc, sm);

    int lane = threadIdx.x & 31;
    int wid  = threadIdx.x >> 5;
    int g = lane >> 2, m = lane & 3;
    int wm = wid & 3, wn = wid >> 2;

#pragma unroll
    for (int im = 0; im < 2; im++) {
        int r0 = bm + wm * 32 + im * 16 + g;
#pragma unroll
        for (int jn = 0; jn < 8; jn++) {
            int n = bn + wn * 64 + jn * 8 + 2 * m;
            float b0v = bias[n], b1v = bias[n + 1];
            float* o0 = C + (size_t)r0 * EMB + n;
            float* o1 = o0 + (size_t)8 * EMB;
            *(float2*)o0 = make_float2(acc.a[im][jn][0] + b0v, acc.a[im][jn][1] + b1v);
            *(float2*)o1 = make_float2(acc.a[im][jn][2] + b0v, acc.a[im][jn][3] + b1v);
        }
    }
}

// ---------------------------------------------------------------------------
// Flash attention v2 (from R6, proven 210us). Epilogue now writes g_O
// tf32-rounded (same value oproj used to compute at its load -> identical).
// ---------------------------------------------------------------------------
#define KVS    72
#define TILE_F (64 * KVS)
#define ATT_SMEM (4 * TILE_F * 4)

__global__ void __launch_bounds__(128) attn_tc2_kernel(
    const float* __restrict__ mask,
    const float* __restrict__ attn_bias,
    const float* __restrict__ beta_p,
    const float* __restrict__ bbias_p)
{
    extern __shared__ __align__(16) float sm[];

    int qt   = blockIdx.x;
    int bh   = blockIdx.y;
    int b    = bh / NH;
    int h    = bh % NH;
    int q0   = qt * 128;
    int tid  = threadIdx.x;
    int w    = tid >> 5;
    int lane = tid & 31;
    int g    = lane >> 2;
    int m    = lane & 3;

    const float beta  = beta_p[0];
    const float bbias = bbias_p[0];
    const int masknz  = g_mask_nz;

    const float* Kg    = g_K + (size_t)bh * SEQ * HD;
    const float* Vg    = g_V + (size_t)bh * SEQ * HD;
    const float* biasg = attn_bias + (size_t)bh * SEQ;

    unsigned qf[2][8][4];
    {
        const float* Qb = g_Q + ((size_t)bh * SEQ + q0 + w * 32) * HD;
#pragma unroll
        for (int im = 0; im < 2; im++) {
            const float* r0 = Qb + (size_t)(im * 16 + g) * HD;
            const float* r1 = r0 + 8 * HD;
#pragma unroll
            for (int t = 0; t < 8; t++) {
                qf[im][t][0] = __float_as_uint(r0[8 * t + m]);
                qf[im][t][1] = __float_as_uint(r1[8 * t + m]);
                qf[im][t][2] = __float_as_uint(r0[8 * t + m + 4]);
                qf[im][t][3] = __float_as_uint(r1[8 * t + m + 4]);
            }
        }
    }

    float mr[2][2], lrn[2][2];
    float oa[2][8][4];
#pragma unroll
    for (int im = 0; im < 2; im++) {
        mr[im][0] = -1e30f; mr[im][1] = -1e30f;
        lrn[im][0] = 0.f;   lrn[im][1] = 0.f;
#pragma unroll
        for (int d = 0; d < 8; d++)
#pragma unroll
            for (int i = 0; i < 4; i++) oa[im][d][i] = 0.f;
    }

    unsigned sbase = (unsigned)__cvta_generic_to_shared(sm);
    int lrow = tid >> 4;
    int cir  = tid & 15;

    auto issue_tile = [&](int kt) {
        unsigned kst = sbase + (unsigned)(kt & 1) * (2 * TILE_F * 4);
        unsigned vst = kst + TILE_F * 4;
        const float* kp = Kg + (size_t)(kt * 64) * HD;
        const float* vp = Vg + (size_t)(kt * 64) * HD;
#pragma unroll
        for (int u = 0; u < 8; u++) {
            int row = u * 8 + lrow;
            unsigned soff = (unsigned)(row * KVS + cir * 4) * 4;
            cp_async16(kst + soff, kp + (size_t)row * HD + cir * 4);
            cp_async16(vst + soff, vp + (size_t)row * HD + cir * 4);
        }
        cp_commit();
    };

    issue_tile(0);

    const int NT = SEQ / 64;
    for (int kt = 0; kt < NT; kt++) {
        if (kt + 1 < NT) { issue_tile(kt + 1); cp_wait<1>(); }
        else             { cp_wait<0>(); }
        __syncthreads();

        const float* Ksb = sm + (kt & 1) * 2 * TILE_F;
        const float* Vsb = Ksb + TILE_F;
        int k0 = kt * 64;

        float sc[2][8][4];
#pragma unroll
        for (int im = 0; im < 2; im++)
#pragma unroll
            for (int j = 0; j < 8; j++)
#pragma unroll
                for (int i = 0; i < 4; i++) sc[im][j][i] = 0.f;

#pragma unroll
        for (int t = 0; t < 8; t++) {
#pragma unroll
            for (int j = 0; j < 8; j++) {
                const float* kr = Ksb + (8 * j + g) * KVS + 8 * t + m;
                unsigned b0 = __float_as_uint(kr[0]);
                unsigned b1 = __float_as_uint(kr[4]);
                mma_tf32(sc[0][j], qf[0][t], b0, b1);
                mma_tf32(sc[1][j], qf[1][t], b0, b1);
            }
        }

#pragma unroll
        for (int j = 0; j < 8; j++) {
            float2 bv = *(const float2*)(biasg + k0 + 8 * j + 2 * m);
            float b0v = beta * bv.x + bbias;
            float b1v = beta * bv.y + bbias;
#pragma unroll
            for (int im = 0; im < 2; im++) {
                sc[im][j][0] += b0v; sc[im][j][1] += b1v;
                sc[im][j][2] += b0v; sc[im][j][3] += b1v;
                if (masknz) {
                    int qr = q0 + w * 32 + im * 16 + g;
                    const float* m0p = mask + ((size_t)b * SEQ + qr) * SEQ + k0 + 8 * j + 2 * m;
                    const float* m1p = m0p + (size_t)8 * SEQ;
                    sc[im][j][0] += m0p[0]; sc[im][j][1] += m0p[1];
                    sc[im][j][2] += m1p[0]; sc[im][j][3] += m1p[1];
                }
            }
        }

#pragma unroll
        for (int im = 0; im < 2; im++) {
            float mx0 = sc[im][0][0], mx1 = sc[im][0][2];
#pragma unroll
            for (int j = 0; j < 8; j++) {
                mx0 = fmaxf(mx0, fmaxf(sc[im][j][0], sc[im][j][1]));
                mx1 = fmaxf(mx1, fmaxf(sc[im][j][2], sc[im][j][3]));
            }
            mx0 = fmaxf(mx0, __shfl_xor_sync(0xffffffffu, mx0, 1));
            mx0 = fmaxf(mx0, __shfl_xor_sync(0xffffffffu, mx0, 2));
            mx1 = fmaxf(mx1, __shfl_xor_sync(0xffffffffu, mx1, 1));
            mx1 = fmaxf(mx1, __shfl_xor_sync(0xffffffffu, mx1, 2));

            float mn0 = fmaxf(mr[im][0], mx0);
            float mn1 = fmaxf(mr[im][1], mx1);
            float al0 = __expf(mr[im][0] - mn0);
            float al1 = __expf(mr[im][1] - mn1);

            float s0 = 0.f, s1 = 0.f;
#pragma unroll
            for (int j = 0; j < 8; j++) {
                sc[im][j][0] = __expf(sc[im][j][0] - mn0);
                sc[im][j][1] = __expf(sc[im][j][1] - mn0);
                sc[im][j][2] = __expf(sc[im][j][2] - mn1);
                sc[im][j][3] = __expf(sc[im][j][3] - mn1);
                s0 += sc[im][j][0] + sc[im][j][1];
                s1 += sc[im][j][2] + sc[im][j][3];
            }
            s0 += __shfl_xor_sync(0xffffffffu, s0, 1);
            s0 += __shfl_xor_sync(0xffffffffu, s0, 2);
            s1 += __shfl_xor_sync(0xffffffffu, s1, 1);
            s1 += __shfl_xor_sync(0xffffffffu, s1, 2);

            lrn[im][0] = lrn[im][0] * al0 + s0;
            lrn[im][1] = lrn[im][1] * al1 + s1;
            mr[im][0] = mn0; mr[im][1] = mn1;
#pragma unroll
            for (int d = 0; d < 8; d++) {
                oa[im][d][0] *= al0; oa[im][d][1] *= al0;
                oa[im][d][2] *= al1; oa[im][d][3] *= al1;
            }
        }

        int src0 = (lane & ~3) | (m >> 1);
        int src1 = src0 + 2;
        int sel  = m & 1;
#pragma unroll
        for (int j = 0; j < 8; j++) {
            unsigned pa[2][4];
#pragma unroll
            for (int im = 0; im < 2; im++) {
                unsigned p0 = cvt_tf32(sc[im][j][0]);
                unsigned p1 = cvt_tf32(sc[im][j][1]);
                unsigned p2 = cvt_tf32(sc[im][j][2]);
                unsigned p3 = cvt_tf32(sc[im][j][3]);
                unsigned x0 = __shfl_sync(0xffffffffu, p0, src0);
                unsigned x1 = __shfl_sync(0xffffffffu, p1, src0);
                pa[im][0] = sel ? x1 : x0;
                unsigned x2 = __shfl_sync(0xffffffffu, p2, src0);
                unsigned x3 = __shfl_sync(0xffffffffu, p3, src0);
                pa[im][1] = sel ? x3 : x2;
                unsigned y0 = __shfl_sync(0xffffffffu, p0, src1);
                unsigned y1 = __shfl_sync(0xffffffffu, p1, src1);
                pa[im][2] = sel ? y1 : y0;
                unsigned y2 = __shfl_sync(0xffffffffu, p2, src1);
                unsigned y3 = __shfl_sync(0xffffffffu, p3, src1);
                pa[im][3] = sel ? y3 : y2;
            }
#pragma unroll
            for (int d = 0; d < 8; d++) {
                const float* vr = Vsb + (8 * j + m) * KVS + 8 * d + g;
                unsigned b0 = __float_as_uint(vr[0]);
                unsigned b1 = __float_as_uint(vr[4 * KVS]);
                mma_tf32(oa[0][d], pa[0], b0, b1);
                mma_tf32(oa[1][d], pa[1], b0, b1);
            }
        }
        __syncthreads();
    }

    // Epilogue: tf32-rounded O (same value oproj consumed before)
#pragma unroll
    for (int im = 0; im < 2; im++) {
        float inv0 = 1.f / lrn[im][0];
        float inv1 = 1.f / lrn[im][1];
        int qr = q0 + w * 32 + im * 16 + g;
        float* O0 = g_O + ((size_t)(b * SEQ + qr)) * EMB + h * HD;
        float* O1 = O0 + (size_t)8 * EMB;
#pragma unroll
        for (int d = 0; d < 8; d++) {
            int c = 8 * d + 2 * m;
            *(float2*)(O0 + c) = make_float2(cvt_tf32_f(oa[im][d][0] * inv0),
                                             cvt_tf32_f(oa[im][d][1] * inv0));
            *(float2*)(O1 + c) = make_float2(cvt_tf32_f(oa[im][d][2] * inv1),
                                             cvt_tf32_f(oa[im][d][3] * inv1));
        }
    }
}

// ---------------------------------------------------------------------------
// Launch
// ---------------------------------------------------------------------------
extern "C" void kernel_launch(void* const* d_in, const int* in_sizes, int n_in,
                              void* d_out, int out_size) {
    const float* X     = (const float*)d_in[0];
    const float* mask  = (const float*)d_in[1];
    const float* abias = (const float*)d_in[2];
    const float* Wq    = (const float*)d_in[3];
    const float* bq    = (const float*)d_in[4];
    const float* Wk    = (const float*)d_in[5];
    const float* bk    = (const float*)d_in[6];
    const float* Wv    = (const float*)d_in[7];
    const float* bv    = (const float*)d_in[8];
    const float* Wo    = (const float*)d_in[9];
    const float* bo    = (const float*)d_in[10];
    const float* beta  = (const float*)d_in[11];
    const float* bbias = (const float*)d_in[12];
    float* out = (float*)d_out;

    cudaFuncSetAttribute(attn_tc2_kernel,
                         cudaFuncAttributeMaxDynamicSharedMemorySize, ATT_SMEM);
    cudaFuncSetAttribute(qkv_gemm_pipe_kernel,
                         cudaFuncAttributeMaxDynamicSharedMemorySize, GEMM_SMEM);
    cudaFuncSetAttribute(oproj_gemm_pipe_kernel,
                         cudaFuncAttributeMaxDynamicSharedMemorySize, GEMM_SMEM);

    reset_flag_kernel<<<1, 32>>>();
    scan_mask_kernel<<<1024, 256>>>(mask, BSZ * SEQ * SEQ / 4);
    round_inputs_kernel<<<512, 256>>>(X, Wq, Wk, Wv, Wo);
    qkv_gemm_pipe_kernel<<<dim3(18, 32), 256, GEMM_SMEM>>>(bq, bk, bv);
    attn_tc2_kernel<<<dim3(SEQ / 128, BH), 128, ATT_SMEM>>>(mask, abias, beta, bbias);
    oproj_gemm_pipe_kernel<<<dim3(6, 32), 256, GEMM_SMEM>>>(bo, out);
}

// round 8
// speedup vs baseline: 1.0200x; 1.0200x over previous
#include <cuda_runtime.h>
#include <stdint.h>
#include <math.h>

#define BSZ 2
#define SEQ 2048
#define EMB 768
#define NH  12
#define HD  64
#define BH  (BSZ*NH)     /* 24  */
#define MTOK (BSZ*SEQ)   /* 4096 */

// ---------------------------------------------------------------------------
// Scratch
// ---------------------------------------------------------------------------
__device__ float g_Q[BH * SEQ * HD];
__device__ float g_K[BH * SEQ * HD];
__device__ float g_V[BH * SEQ * HD];
__device__ float g_O[MTOK * EMB];          // attention out, tf32-rounded
__device__ float g_X[MTOK * EMB];          // tf32-rounded hidden states
__device__ float g_W4[4 * EMB * EMB];      // tf32-rounded Wq,Wk,Wv,Wo
__device__ int   g_mask_nz;

// ---------------------------------------------------------------------------
// Mask scan
// ---------------------------------------------------------------------------
__global__ void reset_flag_kernel() { g_mask_nz = 0; }

__global__ void scan_mask_kernel(const float* __restrict__ mask, int n4) {
    int i = blockIdx.x * blockDim.x + threadIdx.x;
    int stride = gridDim.x * blockDim.x;
    int nz = 0;
    for (; i < n4; i += stride) {
        float4 v = ((const float4*)mask)[i];
        nz |= (v.x != 0.f) | (v.y != 0.f) | (v.z != 0.f) | (v.w != 0.f);
    }
    if (__syncthreads_or(nz)) {
        if (threadIdx.x == 0) atomicOr(&g_mask_nz, 1);
    }
}

// ---------------------------------------------------------------------------
// tf32 / cp.async helpers
// ---------------------------------------------------------------------------
__device__ __forceinline__ unsigned cvt_tf32(float x) {
    unsigned r;
    asm("cvt.rna.tf32.f32 %0, %1;" : "=r"(r) : "f"(x));
    return r;
}
__device__ __forceinline__ float cvt_tf32_f(float x) {
    return __uint_as_float(cvt_tf32(x));
}

__device__ __forceinline__ void mma_tf32(float c[4], const unsigned a[4],
                                         unsigned b0, unsigned b1) {
    asm("mma.sync.aligned.m16n8k8.row.col.f32.tf32.tf32.f32 "
        "{%0,%1,%2,%3},{%4,%5,%6,%7},{%8,%9},{%0,%1,%2,%3};"
        : "+f"(c[0]), "+f"(c[1]), "+f"(c[2]), "+f"(c[3])
        : "r"(a[0]), "r"(a[1]), "r"(a[2]), "r"(a[3]), "r"(b0), "r"(b1));
}

__device__ __forceinline__ void cp_async16(unsigned saddr, const void* gptr) {
    asm volatile("cp.async.cg.shared.global [%0], [%1], 16;"
                 :: "r"(saddr), "l"(gptr));
}
__device__ __forceinline__ void cp_commit() {
    asm volatile("cp.async.commit_group;");
}
template <int N>
__device__ __forceinline__ void cp_wait() {
    asm volatile("cp.async.wait_group %0;" :: "n"(N));
}

// ---------------------------------------------------------------------------
// Pre-round pass: X and the 4 weight matrices -> tf32 (rna), into scratch.
// ---------------------------------------------------------------------------
__global__ void round_inputs_kernel(
    const float* __restrict__ X,
    const float* __restrict__ Wq, const float* __restrict__ Wk,
    const float* __restrict__ Wv, const float* __restrict__ Wo)
{
    int i = blockIdx.x * blockDim.x + threadIdx.x;
    int stride = gridDim.x * blockDim.x;
    const int NX = MTOK * EMB / 4;
    const int NW = EMB * EMB / 4;
    for (int k = i; k < NX; k += stride) {
        float4 v = ((const float4*)X)[k];
        v.x = cvt_tf32_f(v.x); v.y = cvt_tf32_f(v.y);
        v.z = cvt_tf32_f(v.z); v.w = cvt_tf32_f(v.w);
        ((float4*)g_X)[k] = v;
    }
    const float* Ws[4] = {Wq, Wk, Wv, Wo};
#pragma unroll
    for (int s = 0; s < 4; s++) {
        float4* dst = (float4*)(g_W4 + (size_t)s * EMB * EMB);
        const float4* src = (const float4*)Ws[s];
        for (int k = i; k < NW; k += stride) {
            float4 v = src[k];
            v.x = cvt_tf32_f(v.x); v.y = cvt_tf32_f(v.y);
            v.z = cvt_tf32_f(v.z); v.w = cvt_tf32_f(v.w);
            dst[k] = v;
        }
    }
}

// ---------------------------------------------------------------------------
// Pipelined tf32 GEMM core v2: 3-stage cp.async, ONE sync per iteration.
// C(128x128) = A(128xEMB) @ W^T(128xEMB), operands pre-rounded tf32.
// 256 thr = 8 warps (4m x 2n), warp tile 32x64. BK=32.
// Per iter: wait(stage it) -> sync -> issue(it+2) -> compute(it).
// issue(it+2) overwrites buffer (it-1)%3; the sync guarantees all warps
// finished compute(it-1), so the single barrier is sufficient.
// ---------------------------------------------------------------------------
#define DSW 36
#define GST (128 * DSW)                 /* floats per operand per stage */
#define NSTG 3
#define GEMM_SMEM (NSTG * 2 * GST * 4)  /* 110592 bytes */

struct GemmAcc { float a[2][8][4]; };

__device__ __forceinline__ void gemm_pipe_core(
    const float* __restrict__ A, const float* __restrict__ W,
    int bm, int bn, GemmAcc& acc, float* sm)
{
    int tid = threadIdx.x;
    int lane = tid & 31;
    int wid = tid >> 5;
    int g = lane >> 2, m = lane & 3;
    int wm = wid & 3, wn = wid >> 2;

#pragma unroll
    for (int im = 0; im < 2; im++)
#pragma unroll
        for (int jn = 0; jn < 8; jn++)
#pragma unroll
            for (int i = 0; i < 4; i++) acc.a[im][jn][i] = 0.f;

    unsigned sbase = (unsigned)__cvta_generic_to_shared(sm);
    int rowc = tid >> 1;            // 0..127
    int cOff = (tid & 1) * 4;       // 0 or 4 (4-float units)
    const float* agp = A + (size_t)(bm + rowc) * EMB + cOff * 4;
    const float* bgp = W + (size_t)(bn + rowc) * EMB + cOff * 4;
    unsigned soff = (unsigned)(rowc * DSW + cOff * 4) * 4;

    auto issue = [&](int it) {
        int st = it % NSTG;
        unsigned as = sbase + (unsigned)st * (2 * GST * 4);
        unsigned bs = as + GST * 4;
        int k0 = it * 32;
#pragma unroll
        for (int u = 0; u < 4; u++) {
            cp_async16(as + soff + u * 16, agp + k0 + u * 4);
            cp_async16(bs + soff + u * 16, bgp + k0 + u * 4);
        }
        cp_commit();
    };

    const int NIT = EMB / 32;   // 24
    issue(0);
    issue(1);

    for (int it = 0; it < NIT; it++) {
        if (it + 1 < NIT) cp_wait<1>();
        else              cp_wait<0>();
        __syncthreads();
        if (it + 2 < NIT) issue(it + 2);

        const float* As = sm + (it % NSTG) * 2 * GST;
        const float* Bs = As + GST;

#pragma unroll
        for (int t = 0; t < 4; t++) {
            unsigned af[2][4];
#pragma unroll
            for (int im = 0; im < 2; im++) {
                const float* ab = As + (wm * 32 + im * 16 + g) * DSW + 8 * t + m;
                af[im][0] = __float_as_uint(ab[0]);
                af[im][2] = __float_as_uint(ab[4]);
                af[im][1] = __float_as_uint(ab[8 * DSW]);
                af[im][3] = __float_as_uint(ab[8 * DSW + 4]);
            }
#pragma unroll
            for (int jn = 0; jn < 8; jn++) {
                const float* bb = Bs + (wn * 64 + jn * 8 + g) * DSW + 8 * t + m;
                unsigned b0 = __float_as_uint(bb[0]);
                unsigned b1 = __float_as_uint(bb[4]);
                mma_tf32(acc.a[0][jn], af[0], b0, b1);
                mma_tf32(acc.a[1][jn], af[1], b0, b1);
            }
        }
    }
}

// ---------------------------------------------------------------------------
// QKV projection: grid (18, 32). Writes [bh][s][d], tf32-rounded (Q scaled).
// ---------------------------------------------------------------------------
__global__ void __launch_bounds__(256) qkv_gemm_pipe_kernel(
    const float* __restrict__ bq, const float* __restrict__ bk,
    const float* __restrict__ bv)
{
    extern __shared__ __align__(16) float sm[];

    int bx  = blockIdx.x;
    int seg = bx / 6;
    int nb  = bx % 6;
    int bm  = blockIdx.y * 128;

    const float* W    = g_W4 + (size_t)seg * EMB * EMB;
    const float* bias = (seg == 0) ? bq : (seg == 1) ? bk : bv;
    float*       out  = (seg == 0) ? g_Q : (seg == 1) ? g_K : g_V;
    const float scale = (seg == 0) ? 0.125f : 1.0f;

    GemmAcc acc;
    gemm_pipe_core(g_X, W, bm, nb * 128, acc, sm);

    int lane = threadIdx.x & 31;
    int wid  = threadIdx.x >> 5;
    int g = lane >> 2, m = lane & 3;
    int wm = wid & 3, wn = wid >> 2;

#pragma unroll
    for (int im = 0; im < 2; im++) {
        int r0 = bm + wm * 32 + im * 16 + g;
#pragma unroll
        for (int jn = 0; jn < 8; jn++) {
            int nloc = nb * 128 + wn * 64 + jn * 8 + 2 * m;
            int h = nloc >> 6, d = nloc & 63;
            float b0v = bias[nloc], b1v = bias[nloc + 1];
            int b = r0 >> 11, s0 = r0 & 2047;
            float* o0 = out + ((size_t)((b * NH + h) * SEQ + s0)) * HD + d;
            float* o1 = o0 + (size_t)8 * HD;
            *(float2*)o0 = make_float2(cvt_tf32_f((acc.a[im][jn][0] + b0v) * scale),
                                       cvt_tf32_f((acc.a[im][jn][1] + b1v) * scale));
            *(float2*)o1 = make_float2(cvt_tf32_f((acc.a[im][jn][2] + b0v) * scale),
                                       cvt_tf32_f((acc.a[im][jn][3] + b1v) * scale));
        }
    }
}

// ---------------------------------------------------------------------------
// Output projection: grid (6, 32). d_out = g_O @ Wo^T + bo (fp32 out).
// ---------------------------------------------------------------------------
__global__ void __launch_bounds__(256) oproj_gemm_pipe_kernel(
    const float* __restrict__ bias, float* __restrict__ C)
{
    extern __shared__ __align__(16) float sm[];

    int bn = blockIdx.x * 128;
    int bm = blockIdx.y * 128;

    GemmAcc acc;
    gemm_pipe_core(g_O, g_W4 + (size_t)3 * EMB * EMB, bm, bn, acc, sm);

    int lane = threadIdx.x & 31;
    int wid  = threadIdx.x >> 5;
    int g = lane >> 2, m = lane & 3;
    int wm = wid & 3, wn = wid >> 2;

#pragma unroll
    for (int im = 0; im < 2; im++) {
        int r0 = bm + wm * 32 + im * 16 + g;
#pragma unroll
        for (int jn = 0; jn < 8; jn++) {
            int n = bn + wn * 64 + jn * 8 + 2 * m;
            float b0v = bias[n], b1v = bias[n + 1];
            float* o0 = C + (size_t)r0 * EMB + n;
            float* o1 = o0 + (size_t)8 * EMB;
            *(float2*)o0 = make_float2(acc.a[im][jn][0] + b0v, acc.a[im][jn][1] + b1v);
            *(float2*)o1 = make_float2(acc.a[im][jn][2] + b0v, acc.a[im][jn][3] + b1v);
        }
    }
}

// ---------------------------------------------------------------------------
// Flash attention v2 (proven 210us, unchanged).
// ---------------------------------------------------------------------------
#define KVS    72
#define TILE_F (64 * KVS)
#define ATT_SMEM (4 * TILE_F * 4)

__global__ void __launch_bounds__(128) attn_tc2_kernel(
    const float* __restrict__ mask,
    const float* __restrict__ attn_bias,
    const float* __restrict__ beta_p,
    const float* __restrict__ bbias_p)
{
    extern __shared__ __align__(16) float sm[];

    int qt   = blockIdx.x;
    int bh   = blockIdx.y;
    int b    = bh / NH;
    int h    = bh % NH;
    int q0   = qt * 128;
    int tid  = threadIdx.x;
    int w    = tid >> 5;
    int lane = tid & 31;
    int g    = lane >> 2;
    int m    = lane & 3;

    const float beta  = beta_p[0];
    const float bbias = bbias_p[0];
    const int masknz  = g_mask_nz;

    const float* Kg    = g_K + (size_t)bh * SEQ * HD;
    const float* Vg    = g_V + (size_t)bh * SEQ * HD;
    const float* biasg = attn_bias + (size_t)bh * SEQ;

    unsigned qf[2][8][4];
    {
        const float* Qb = g_Q + ((size_t)bh * SEQ + q0 + w * 32) * HD;
#pragma unroll
        for (int im = 0; im < 2; im++) {
            const float* r0 = Qb + (size_t)(im * 16 + g) * HD;
            const float* r1 = r0 + 8 * HD;
#pragma unroll
            for (int t = 0; t < 8; t++) {
                qf[im][t][0] = __float_as_uint(r0[8 * t + m]);
                qf[im][t][1] = __float_as_uint(r1[8 * t + m]);
                qf[im][t][2] = __float_as_uint(r0[8 * t + m + 4]);
                qf[im][t][3] = __float_as_uint(r1[8 * t + m + 4]);
            }
        }
    }

    float mr[2][2], lrn[2][2];
    float oa[2][8][4];
#pragma unroll
    for (int im = 0; im < 2; im++) {
        mr[im][0] = -1e30f; mr[im][1] = -1e30f;
        lrn[im][0] = 0.f;   lrn[im][1] = 0.f;
#pragma unroll
        for (int d = 0; d < 8; d++)
#pragma unroll
            for (int i = 0; i < 4; i++) oa[im][d][i] = 0.f;
    }

    unsigned sbase = (unsigned)__cvta_generic_to_shared(sm);
    int lrow = tid >> 4;
    int cir  = tid & 15;

    auto issue_tile = [&](int kt) {
        unsigned kst = sbase + (unsigned)(kt & 1) * (2 * TILE_F * 4);
        unsigned vst = kst + TILE_F * 4;
        const float* kp = Kg + (size_t)(kt * 64) * HD;
        const float* vp = Vg + (size_t)(kt * 64) * HD;
#pragma unroll
        for (int u = 0; u < 8; u++) {
            int row = u * 8 + lrow;
            unsigned soff = (unsigned)(row * KVS + cir * 4) * 4;
            cp_async16(kst + soff, kp + (size_t)row * HD + cir * 4);
            cp_async16(vst + soff, vp + (size_t)row * HD + cir * 4);
        }
        cp_commit();
    };

    issue_tile(0);

    const int NT = SEQ / 64;
    for (int kt = 0; kt < NT; kt++) {
        if (kt + 1 < NT) { issue_tile(kt + 1); cp_wait<1>(); }
        else             { cp_wait<0>(); }
        __syncthreads();

        const float* Ksb = sm + (kt & 1) * 2 * TILE_F;
        const float* Vsb = Ksb + TILE_F;
        int k0 = kt * 64;

        float sc[2][8][4];
#pragma unroll
        for (int im = 0; im < 2; im++)
#pragma unroll
            for (int j = 0; j < 8; j++)
#pragma unroll
                for (int i = 0; i < 4; i++) sc[im][j][i] = 0.f;

#pragma unroll
        for (int t = 0; t < 8; t++) {
#pragma unroll
            for (int j = 0; j < 8; j++) {
                const float* kr = Ksb + (8 * j + g) * KVS + 8 * t + m;
                unsigned b0 = __float_as_uint(kr[0]);
                unsigned b1 = __float_as_uint(kr[4]);
                mma_tf32(sc[0][j], qf[0][t], b0, b1);
                mma_tf32(sc[1][j], qf[1][t], b0, b1);
            }
        }

#pragma unroll
        for (int j = 0; j < 8; j++) {
            float2 bv = *(const float2*)(biasg + k0 + 8 * j + 2 * m);
            float b0v = beta * bv.x + bbias;
            float b1v = beta * bv.y + bbias;
#pragma unroll
            for (int im = 0; im < 2; im++) {
                sc[im][j][0] += b0v; sc[im][j][1] += b1v;
                sc[im][j][2] += b0v; sc[im][j][3] += b1v;
                if (masknz) {
                    int qr = q0 + w * 32 + im * 16 + g;
                    const float* m0p = mask + ((size_t)b * SEQ + qr) * SEQ + k0 + 8 * j + 2 * m;
                    const float* m1p = m0p + (size_t)8 * SEQ;
                    sc[im][j][0] += m0p[0]; sc[im][j][1] += m0p[1];
                    sc[im][j][2] += m1p[0]; sc[im][j][3] += m1p[1];
                }
            }
        }

#pragma unroll
        for (int im = 0; im < 2; im++) {
            float mx0 = sc[im][0][0], mx1 = sc[im][0][2];
#pragma unroll
            for (int j = 0; j < 8; j++) {
                mx0 = fmaxf(mx0, fmaxf(sc[im][j][0], sc[im][j][1]));
                mx1 = fmaxf(mx1, fmaxf(sc[im][j][2], sc[im][j][3]));
            }
            mx0 = fmaxf(mx0, __shfl_xor_sync(0xffffffffu, mx0, 1));
            mx0 = fmaxf(mx0, __shfl_xor_sync(0xffffffffu, mx0, 2));
            mx1 = fmaxf(mx1, __shfl_xor_sync(0xffffffffu, mx1, 1));
            mx1 = fmaxf(mx1, __shfl_xor_sync(0xffffffffu, mx1, 2));

            float mn0 = fmaxf(mr[im][0], mx0);
            float mn1 = fmaxf(mr[im][1], mx1);
            float al0 = __expf(mr[im][0] - mn0);
            float al1 = __expf(mr[im][1] - mn1);

            float s0 = 0.f, s1 = 0.f;
#pragma unroll
            for (int j = 0; j < 8; j++) {
                sc[im][j][0] = __expf(sc[im][j][0] - mn0);
                sc[im][j][1] = __expf(sc[im][j][1] - mn0);
                sc[im][j][2] = __expf(sc[im][j][2] - mn1);
                sc[im][j][3] = __expf(sc[im][j][3] - mn1);
                s0 += sc[im][j][0] + sc[im][j][1];
                s1 += sc[im][j][2] + sc[im][j][3];
            }
            s0 += __shfl_xor_sync(0xffffffffu, s0, 1);
            s0 += __shfl_xor_sync(0xffffffffu, s0, 2);
            s1 += __shfl_xor_sync(0xffffffffu, s1, 1);
            s1 += __shfl_xor_sync(0xffffffffu, s1, 2);

            lrn[im][0] = lrn[im][0] * al0 + s0;
            lrn[im][1] = lrn[im][1] * al1 + s1;
            mr[im][0] = mn0; mr[im][1] = mn1;
#pragma unroll
            for (int d = 0; d < 8; d++) {
                oa[im][d][0] *= al0; oa[im][d][1] *= al0;
                oa[im][d][2] *= al1; oa[im][d][3] *= al1;
            }
        }

        int src0 = (lane & ~3) | (m >> 1);
        int src1 = src0 + 2;
        int sel  = m & 1;
#pragma unroll
        for (int j = 0; j < 8; j++) {
            unsigned pa[2][4];
#pragma unroll
            for (int im = 0; im < 2; im++) {
                unsigned p0 = cvt_tf32(sc[im][j][0]);
                unsigned p1 = cvt_tf32(sc[im][j][1]);
                unsigned p2 = cvt_tf32(sc[im][j][2]);
                unsigned p3 = cvt_tf32(sc[im][j][3]);
                unsigned x0 = __shfl_sync(0xffffffffu, p0, src0);
                unsigned x1 = __shfl_sync(0xffffffffu, p1, src0);
                pa[im][0] = sel ? x1 : x0;
                unsigned x2 = __shfl_sync(0xffffffffu, p2, src0);
                unsigned x3 = __shfl_sync(0xffffffffu, p3, src0);
                pa[im][1] = sel ? x3 : x2;
                unsigned y0 = __shfl_sync(0xffffffffu, p0, src1);
                unsigned y1 = __shfl_sync(0xffffffffu, p1, src1);
                pa[im][2] = sel ? y1 : y0;
                unsigned y2 = __shfl_sync(0xffffffffu, p2, src1);
                unsigned y3 = __shfl_sync(0xffffffffu, p3, src1);
                pa[im][3] = sel ? y3 : y2;
            }
#pragma unroll
            for (int d = 0; d < 8; d++) {
                const float* vr = Vsb + (8 * j + m) * KVS + 8 * d + g;
                unsigned b0 = __float_as_uint(vr[0]);
                unsigned b1 = __float_as_uint(vr[4 * KVS]);
                mma_tf32(oa[0][d], pa[0], b0, b1);
                mma_tf32(oa[1][d], pa[1], b0, b1);
            }
        }
        __syncthreads();
    }

#pragma unroll
    for (int im = 0; im < 2; im++) {
        float inv0 = 1.f / lrn[im][0];
        float inv1 = 1.f / lrn[im][1];
        int qr = q0 + w * 32 + im * 16 + g;
        float* O0 = g_O + ((size_t)(b * SEQ + qr)) * EMB + h * HD;
        float* O1 = O0 + (size_t)8 * EMB;
#pragma unroll
        for (int d = 0; d < 8; d++) {
            int c = 8 * d + 2 * m;
            *(float2*)(O0 + c) = make_float2(cvt_tf32_f(oa[im][d][0] * inv0),
                                             cvt_tf32_f(oa[im][d][1] * inv0));
            *(float2*)(O1 + c) = make_float2(cvt_tf32_f(oa[im][d][2] * inv1),
                                             cvt_tf32_f(oa[im][d][3] * inv1));
        }
    }
}

// ---------------------------------------------------------------------------
// Launch
// ---------------------------------------------------------------------------
extern "C" void kernel_launch(void* const* d_in, const int* in_sizes, int n_in,
                              void* d_out, int out_size) {
    const float* X     = (const float*)d_in[0];
    const float* mask  = (const float*)d_in[1];
    const float* abias = (const float*)d_in[2];
    const float* Wq    = (const float*)d_in[3];
    const float* bq    = (const float*)d_in[4];
    const float* Wk    = (const float*)d_in[5];
    const float* bk    = (const float*)d_in[6];
    const float* Wv    = (const float*)d_in[7];
    const float* bv    = (const float*)d_in[8];
    const float* Wo    = (const float*)d_in[9];
    const float* bo    = (const float*)d_in[10];
    const float* beta  = (const float*)d_in[11];
    const float* bbias = (const float*)d_in[12];
    float* out = (float*)d_out;

    cudaFuncSetAttribute(attn_tc2_kernel,
                         cudaFuncAttributeMaxDynamicSharedMemorySize, ATT_SMEM);
    cudaFuncSetAttribute(qkv_gemm_pipe_kernel,
                         cudaFuncAttributeMaxDynamicSharedMemorySize, GEMM_SMEM);
    cudaFuncSetAttribute(oproj_gemm_pipe_kernel,
                         cudaFuncAttributeMaxDynamicSharedMemorySize, GEMM_SMEM);

    reset_flag_kernel<<<1, 32>>>();
    scan_mask_kernel<<<1024, 256>>>(mask, BSZ * SEQ * SEQ / 4);
    round_inputs_kernel<<<512, 256>>>(X, Wq, Wk, Wv, Wo);
    qkv_gemm_pipe_kernel<<<dim3(18, 32), 256, GEMM_SMEM>>>(bq, bk, bv);
    attn_tc2_kernel<<<dim3(SEQ / 128, BH), 128, ATT_SMEM>>>(mask, abias, beta, bbias);
    oproj_gemm_pipe_kernel<<<dim3(6, 32), 256, GEMM_SMEM>>>(bo, out);
}

// round 9
// speedup vs baseline: 1.0699x; 1.0490x over previous
#include <cuda_runtime.h>
#include <stdint.h>
#include <math.h>

#define BSZ 2
#define SEQ 2048
#define EMB 768
#define NH  12
#define HD  64
#define BH  (BSZ*NH)     /* 24  */
#define MTOK (BSZ*SEQ)   /* 4096 */

// ---------------------------------------------------------------------------
// Scratch
// ---------------------------------------------------------------------------
__device__ float g_Q[BH * SEQ * HD];
__device__ float g_K[BH * SEQ * HD];
__device__ float g_V[BH * SEQ * HD];
__device__ float g_O[MTOK * EMB];          // attention out, tf32-rounded
__device__ float g_X[MTOK * EMB];          // tf32-rounded hidden states
__device__ float g_W4[4 * EMB * EMB];      // tf32-rounded Wq,Wk,Wv,Wo
__device__ int   g_mask_nz;

// ---------------------------------------------------------------------------
// Mask scan
// ---------------------------------------------------------------------------
__global__ void reset_flag_kernel() { g_mask_nz = 0; }

__global__ void scan_mask_kernel(const float* __restrict__ mask, int n4) {
    int i = blockIdx.x * blockDim.x + threadIdx.x;
    int stride = gridDim.x * blockDim.x;
    int nz = 0;
    for (; i < n4; i += stride) {
        float4 v = ((const float4*)mask)[i];
        nz |= (v.x != 0.f) | (v.y != 0.f) | (v.z != 0.f) | (v.w != 0.f);
    }
    if (__syncthreads_or(nz)) {
        if (threadIdx.x == 0) atomicOr(&g_mask_nz, 1);
    }
}

// ---------------------------------------------------------------------------
// tf32 / cp.async helpers
// ---------------------------------------------------------------------------
__device__ __forceinline__ unsigned cvt_tf32(float x) {
    unsigned r;
    asm("cvt.rna.tf32.f32 %0, %1;" : "=r"(r) : "f"(x));
    return r;
}
__device__ __forceinline__ float cvt_tf32_f(float x) {
    return __uint_as_float(cvt_tf32(x));
}

__device__ __forceinline__ void mma_tf32(float c[4], const unsigned a[4],
                                         unsigned b0, unsigned b1) {
    asm("mma.sync.aligned.m16n8k8.row.col.f32.tf32.tf32.f32 "
        "{%0,%1,%2,%3},{%4,%5,%6,%7},{%8,%9},{%0,%1,%2,%3};"
        : "+f"(c[0]), "+f"(c[1]), "+f"(c[2]), "+f"(c[3])
        : "r"(a[0]), "r"(a[1]), "r"(a[2]), "r"(a[3]), "r"(b0), "r"(b1));
}

__device__ __forceinline__ void cp_async16(unsigned saddr, const void* gptr) {
    asm volatile("cp.async.cg.shared.global [%0], [%1], 16;"
                 :: "r"(saddr), "l"(gptr));
}
__device__ __forceinline__ void cp_commit() {
    asm volatile("cp.async.commit_group;");
}
template <int N>
__device__ __forceinline__ void cp_wait() {
    asm volatile("cp.async.wait_group %0;" :: "n"(N));
}

// ---------------------------------------------------------------------------
// Pre-round pass: X and the 4 weight matrices -> tf32 (rna), into scratch.
// ---------------------------------------------------------------------------
__global__ void round_inputs_kernel(
    const float* __restrict__ X,
    const float* __restrict__ Wq, const float* __restrict__ Wk,
    const float* __restrict__ Wv, const float* __restrict__ Wo)
{
    int i = blockIdx.x * blockDim.x + threadIdx.x;
    int stride = gridDim.x * blockDim.x;
    const int NX = MTOK * EMB / 4;
    const int NW = EMB * EMB / 4;
    for (int k = i; k < NX; k += stride) {
        float4 v = ((const float4*)X)[k];
        v.x = cvt_tf32_f(v.x); v.y = cvt_tf32_f(v.y);
        v.z = cvt_tf32_f(v.z); v.w = cvt_tf32_f(v.w);
        ((float4*)g_X)[k] = v;
    }
    const float* Ws[4] = {Wq, Wk, Wv, Wo};
#pragma unroll
    for (int s = 0; s < 4; s++) {
        float4* dst = (float4*)(g_W4 + (size_t)s * EMB * EMB);
        const float4* src = (const float4*)Ws[s];
        for (int k = i; k < NW; k += stride) {
            float4 v = src[k];
            v.x = cvt_tf32_f(v.x); v.y = cvt_tf32_f(v.y);
            v.z = cvt_tf32_f(v.z); v.w = cvt_tf32_f(v.w);
            dst[k] = v;
        }
    }
}

// ---------------------------------------------------------------------------
// Pipelined tf32 GEMM core (3-stage, one sync/iter) — unchanged from R8.
// ---------------------------------------------------------------------------
#define DSW 36
#define GST (128 * DSW)
#define NSTG 3
#define GEMM_SMEM (NSTG * 2 * GST * 4)

struct GemmAcc { float a[2][8][4]; };

__device__ __forceinline__ void gemm_pipe_core(
    const float* __restrict__ A, const float* __restrict__ W,
    int bm, int bn, GemmAcc& acc, float* sm)
{
    int tid = threadIdx.x;
    int lane = tid & 31;
    int wid = tid >> 5;
    int g = lane >> 2, m = lane & 3;
    int wm = wid & 3, wn = wid >> 2;

#pragma unroll
    for (int im = 0; im < 2; im++)
#pragma unroll
        for (int jn = 0; jn < 8; jn++)
#pragma unroll
            for (int i = 0; i < 4; i++) acc.a[im][jn][i] = 0.f;

    unsigned sbase = (unsigned)__cvta_generic_to_shared(sm);
    int rowc = tid >> 1;
    int cOff = (tid & 1) * 4;
    const float* agp = A + (size_t)(bm + rowc) * EMB + cOff * 4;
    const float* bgp = W + (size_t)(bn + rowc) * EMB + cOff * 4;
    unsigned soff = (unsigned)(rowc * DSW + cOff * 4) * 4;

    auto issue = [&](int it) {
        int st = it % NSTG;
        unsigned as = sbase + (unsigned)st * (2 * GST * 4);
        unsigned bs = as + GST * 4;
        int k0 = it * 32;
#pragma unroll
        for (int u = 0; u < 4; u++) {
            cp_async16(as + soff + u * 16, agp + k0 + u * 4);
            cp_async16(bs + soff + u * 16, bgp + k0 + u * 4);
        }
        cp_commit();
    };

    const int NIT = EMB / 32;
    issue(0);
    issue(1);

    for (int it = 0; it < NIT; it++) {
        if (it + 1 < NIT) cp_wait<1>();
        else              cp_wait<0>();
        __syncthreads();
        if (it + 2 < NIT) issue(it + 2);

        const float* As = sm + (it % NSTG) * 2 * GST;
        const float* Bs = As + GST;

#pragma unroll
        for (int t = 0; t < 4; t++) {
            unsigned af[2][4];
#pragma unroll
            for (int im = 0; im < 2; im++) {
                const float* ab = As + (wm * 32 + im * 16 + g) * DSW + 8 * t + m;
                af[im][0] = __float_as_uint(ab[0]);
                af[im][2] = __float_as_uint(ab[4]);
                af[im][1] = __float_as_uint(ab[8 * DSW]);
                af[im][3] = __float_as_uint(ab[8 * DSW + 4]);
            }
#pragma unroll
            for (int jn = 0; jn < 8; jn++) {
                const float* bb = Bs + (wn * 64 + jn * 8 + g) * DSW + 8 * t + m;
                unsigned b0 = __float_as_uint(bb[0]);
                unsigned b1 = __float_as_uint(bb[4]);
                mma_tf32(acc.a[0][jn], af[0], b0, b1);
                mma_tf32(acc.a[1][jn], af[1], b0, b1);
            }
        }
    }
}

// ---------------------------------------------------------------------------
// QKV projection: grid (18, 32). Writes [bh][s][d], tf32-rounded (Q scaled).
// ---------------------------------------------------------------------------
__global__ void __launch_bounds__(256) qkv_gemm_pipe_kernel(
    const float* __restrict__ bq, const float* __restrict__ bk,
    const float* __restrict__ bv)
{
    extern __shared__ __align__(16) float sm[];

    int bx  = blockIdx.x;
    int seg = bx / 6;
    int nb  = bx % 6;
    int bm  = blockIdx.y * 128;

    const float* W    = g_W4 + (size_t)seg * EMB * EMB;
    const float* bias = (seg == 0) ? bq : (seg == 1) ? bk : bv;
    float*       out  = (seg == 0) ? g_Q : (seg == 1) ? g_K : g_V;
    const float scale = (seg == 0) ? 0.125f : 1.0f;

    GemmAcc acc;
    gemm_pipe_core(g_X, W, bm, nb * 128, acc, sm);

    int lane = threadIdx.x & 31;
    int wid  = threadIdx.x >> 5;
    int g = lane >> 2, m = lane & 3;
    int wm = wid & 3, wn = wid >> 2;

#pragma unroll
    for (int im = 0; im < 2; im++) {
        int r0 = bm + wm * 32 + im * 16 + g;
#pragma unroll
        for (int jn = 0; jn < 8; jn++) {
            int nloc = nb * 128 + wn * 64 + jn * 8 + 2 * m;
            int h = nloc >> 6, d = nloc & 63;
            float b0v = bias[nloc], b1v = bias[nloc + 1];
            int b = r0 >> 11, s0 = r0 & 2047;
            float* o0 = out + ((size_t)((b * NH + h) * SEQ + s0)) * HD + d;
            float* o1 = o0 + (size_t)8 * HD;
            *(float2*)o0 = make_float2(cvt_tf32_f((acc.a[im][jn][0] + b0v) * scale),
                                       cvt_tf32_f((acc.a[im][jn][1] + b1v) * scale));
            *(float2*)o1 = make_float2(cvt_tf32_f((acc.a[im][jn][2] + b0v) * scale),
                                       cvt_tf32_f((acc.a[im][jn][3] + b1v) * scale));
        }
    }
}

// ---------------------------------------------------------------------------
// Output projection: grid (6, 32). d_out = g_O @ Wo^T + bo (fp32 out).
// ---------------------------------------------------------------------------
__global__ void __launch_bounds__(256) oproj_gemm_pipe_kernel(
    const float* __restrict__ bias, float* __restrict__ C)
{
    extern __shared__ __align__(16) float sm[];

    int bn = blockIdx.x * 128;
    int bm = blockIdx.y * 128;

    GemmAcc acc;
    gemm_pipe_core(g_O, g_W4 + (size_t)3 * EMB * EMB, bm, bn, acc, sm);

    int lane = threadIdx.x & 31;
    int wid  = threadIdx.x >> 5;
    int g = lane >> 2, m = lane & 3;
    int wm = wid & 3, wn = wid >> 2;

#pragma unroll
    for (int im = 0; im < 2; im++) {
        int r0 = bm + wm * 32 + im * 16 + g;
#pragma unroll
        for (int jn = 0; jn < 8; jn++) {
            int n = bn + wn * 64 + jn * 8 + 2 * m;
            float b0v = bias[n], b1v = bias[n + 1];
            float* o0 = C + (size_t)r0 * EMB + n;
            float* o1 = o0 + (size_t)8 * EMB;
            *(float2*)o0 = make_float2(acc.a[im][jn][0] + b0v, acc.a[im][jn][1] + b1v);
            *(float2*)o1 = make_float2(acc.a[im][jn][2] + b0v, acc.a[im][jn][3] + b1v);
        }
    }
}

// ---------------------------------------------------------------------------
// Flash attention v3: shuffle-free PV.
// Key-slot permutation pi(m)=2m, pi(m+4)=2m+1 inside each 8-key block makes
// the P A-fragment equal the lane's own score C-fragment ({c0,c2,c1,c3});
// V rows are read permuted to match (rows 8j+2m, 8j+2m+1). Stride 68 makes
// both K and permuted-V fragment loads bank-conflict-free.
// ---------------------------------------------------------------------------
#define KVS    68
#define TILE_F (64 * KVS)
#define ATT_SMEM (4 * TILE_F * 4)

__global__ void __launch_bounds__(128) attn_tc2_kernel(
    const float* __restrict__ mask,
    const float* __restrict__ attn_bias,
    const float* __restrict__ beta_p,
    const float* __restrict__ bbias_p)
{
    extern __shared__ __align__(16) float sm[];

    int qt   = blockIdx.x;
    int bh   = blockIdx.y;
    int b    = bh / NH;
    int h    = bh % NH;
    int q0   = qt * 128;
    int tid  = threadIdx.x;
    int w    = tid >> 5;
    int lane = tid & 31;
    int g    = lane >> 2;
    int m    = lane & 3;

    const float beta  = beta_p[0];
    const float bbias = bbias_p[0];
    const int masknz  = g_mask_nz;

    const float* Kg    = g_K + (size_t)bh * SEQ * HD;
    const float* Vg    = g_V + (size_t)bh * SEQ * HD;
    const float* biasg = attn_bias + (size_t)bh * SEQ;

    unsigned qf[2][8][4];
    {
        const float* Qb = g_Q + ((size_t)bh * SEQ + q0 + w * 32) * HD;
#pragma unroll
        for (int im = 0; im < 2; im++) {
            const float* r0 = Qb + (size_t)(im * 16 + g) * HD;
            const float* r1 = r0 + 8 * HD;
#pragma unroll
            for (int t = 0; t < 8; t++) {
                qf[im][t][0] = __float_as_uint(r0[8 * t + m]);
                qf[im][t][1] = __float_as_uint(r1[8 * t + m]);
                qf[im][t][2] = __float_as_uint(r0[8 * t + m + 4]);
                qf[im][t][3] = __float_as_uint(r1[8 * t + m + 4]);
            }
        }
    }

    float mr[2][2], lrn[2][2];
    float oa[2][8][4];
#pragma unroll
    for (int im = 0; im < 2; im++) {
        mr[im][0] = -1e30f; mr[im][1] = -1e30f;
        lrn[im][0] = 0.f;   lrn[im][1] = 0.f;
#pragma unroll
        for (int d = 0; d < 8; d++)
#pragma unroll
            for (int i = 0; i < 4; i++) oa[im][d][i] = 0.f;
    }

    unsigned sbase = (unsigned)__cvta_generic_to_shared(sm);
    int lrow = tid >> 4;
    int cir  = tid & 15;

    auto issue_tile = [&](int kt) {
        unsigned kst = sbase + (unsigned)(kt & 1) * (2 * TILE_F * 4);
        unsigned vst = kst + TILE_F * 4;
        const float* kp = Kg + (size_t)(kt * 64) * HD;
        const float* vp = Vg + (size_t)(kt * 64) * HD;
#pragma unroll
        for (int u = 0; u < 8; u++) {
            int row = u * 8 + lrow;
            unsigned soff = (unsigned)(row * KVS + cir * 4) * 4;
            cp_async16(kst + soff, kp + (size_t)row * HD + cir * 4);
            cp_async16(vst + soff, vp + (size_t)row * HD + cir * 4);
        }
        cp_commit();
    };

    issue_tile(0);

    const int NT = SEQ / 64;
    for (int kt = 0; kt < NT; kt++) {
        if (kt + 1 < NT) { issue_tile(kt + 1); cp_wait<1>(); }
        else             { cp_wait<0>(); }
        __syncthreads();

        const float* Ksb = sm + (kt & 1) * 2 * TILE_F;
        const float* Vsb = Ksb + TILE_F;
        int k0 = kt * 64;

        float sc[2][8][4];
#pragma unroll
        for (int im = 0; im < 2; im++)
#pragma unroll
            for (int j = 0; j < 8; j++)
#pragma unroll
                for (int i = 0; i < 4; i++) sc[im][j][i] = 0.f;

#pragma unroll
        for (int t = 0; t < 8; t++) {
#pragma unroll
            for (int j = 0; j < 8; j++) {
                const float* kr = Ksb + (8 * j + g) * KVS + 8 * t + m;
                unsigned b0 = __float_as_uint(kr[0]);
                unsigned b1 = __float_as_uint(kr[4]);
                mma_tf32(sc[0][j], qf[0][t], b0, b1);
                mma_tf32(sc[1][j], qf[1][t], b0, b1);
            }
        }

#pragma unroll
        for (int j = 0; j < 8; j++) {
            float2 bv = *(const float2*)(biasg + k0 + 8 * j + 2 * m);
            float b0v = beta * bv.x + bbias;
            float b1v = beta * bv.y + bbias;
#pragma unroll
            for (int im = 0; im < 2; im++) {
                sc[im][j][0] += b0v; sc[im][j][1] += b1v;
                sc[im][j][2] += b0v; sc[im][j][3] += b1v;
                if (masknz) {
                    int qr = q0 + w * 32 + im * 16 + g;
                    const float* m0p = mask + ((size_t)b * SEQ + qr) * SEQ + k0 + 8 * j + 2 * m;
                    const float* m1p = m0p + (size_t)8 * SEQ;
                    sc[im][j][0] += m0p[0]; sc[im][j][1] += m0p[1];
                    sc[im][j][2] += m1p[0]; sc[im][j][3] += m1p[1];
                }
            }
        }

#pragma unroll
        for (int im = 0; im < 2; im++) {
            float mx0 = sc[im][0][0], mx1 = sc[im][0][2];
#pragma unroll
            for (int j = 0; j < 8; j++) {
                mx0 = fmaxf(mx0, fmaxf(sc[im][j][0], sc[im][j][1]));
                mx1 = fmaxf(mx1, fmaxf(sc[im][j][2], sc[im][j][3]));
            }
            mx0 = fmaxf(mx0, __shfl_xor_sync(0xffffffffu, mx0, 1));
            mx0 = fmaxf(mx0, __shfl_xor_sync(0xffffffffu, mx0, 2));
            mx1 = fmaxf(mx1, __shfl_xor_sync(0xffffffffu, mx1, 1));
            mx1 = fmaxf(mx1, __shfl_xor_sync(0xffffffffu, mx1, 2));

            float mn0 = fmaxf(mr[im][0], mx0);
            float mn1 = fmaxf(mr[im][1], mx1);
            float al0 = __expf(mr[im][0] - mn0);
            float al1 = __expf(mr[im][1] - mn1);

            float s0 = 0.f, s1 = 0.f;
#pragma unroll
            for (int j = 0; j < 8; j++) {
                sc[im][j][0] = __expf(sc[im][j][0] - mn0);
                sc[im][j][1] = __expf(sc[im][j][1] - mn0);
                sc[im][j][2] = __expf(sc[im][j][2] - mn1);
                sc[im][j][3] = __expf(sc[im][j][3] - mn1);
                s0 += sc[im][j][0] + sc[im][j][1];
                s1 += sc[im][j][2] + sc[im][j][3];
            }
            s0 += __shfl_xor_sync(0xffffffffu, s0, 1);
            s0 += __shfl_xor_sync(0xffffffffu, s0, 2);
            s1 += __shfl_xor_sync(0xffffffffu, s1, 1);
            s1 += __shfl_xor_sync(0xffffffffu, s1, 2);

            lrn[im][0] = lrn[im][0] * al0 + s0;
            lrn[im][1] = lrn[im][1] * al1 + s1;
            mr[im][0] = mn0; mr[im][1] = mn1;
#pragma unroll
            for (int d = 0; d < 8; d++) {
                oa[im][d][0] *= al0; oa[im][d][1] *= al0;
                oa[im][d][2] *= al1; oa[im][d][3] *= al1;
            }
        }

        // ---- PV: shuffle-free. A-frag = own C values {c0,c2,c1,c3};
        //      V rows permuted to match: k-slot m -> row 8j+2m,
        //      k-slot m+4 -> row 8j+2m+1. ----
#pragma unroll
        for (int j = 0; j < 8; j++) {
            unsigned pa[2][4];
#pragma unroll
            for (int im = 0; im < 2; im++) {
                pa[im][0] = cvt_tf32(sc[im][j][0]);
                pa[im][1] = cvt_tf32(sc[im][j][2]);
                pa[im][2] = cvt_tf32(sc[im][j][1]);
                pa[im][3] = cvt_tf32(sc[im][j][3]);
            }
            const float* vr = Vsb + (8 * j + 2 * m) * KVS + g;
#pragma unroll
            for (int d = 0; d < 8; d++) {
                unsigned b0 = __float_as_uint(vr[8 * d]);
                unsigned b1 = __float_as_uint(vr[KVS + 8 * d]);
                mma_tf32(oa[0][d], pa[0], b0, b1);
                mma_tf32(oa[1][d], pa[1], b0, b1);
            }
        }
        __syncthreads();
    }

#pragma unroll
    for (int im = 0; im < 2; im++) {
        float inv0 = 1.f / lrn[im][0];
        float inv1 = 1.f / lrn[im][1];
        int qr = q0 + w * 32 + im * 16 + g;
        float* O0 = g_O + ((size_t)(b * SEQ + qr)) * EMB + h * HD;
        float* O1 = O0 + (size_t)8 * EMB;
#pragma unroll
        for (int d = 0; d < 8; d++) {
            int c = 8 * d + 2 * m;
            *(float2*)(O0 + c) = make_float2(cvt_tf32_f(oa[im][d][0] * inv0),
                                             cvt_tf32_f(oa[im][d][1] * inv0));
            *(float2*)(O1 + c) = make_float2(cvt_tf32_f(oa[im][d][2] * inv1),
                                             cvt_tf32_f(oa[im][d][3] * inv1));
        }
    }
}

// ---------------------------------------------------------------------------
// Launch
// ---------------------------------------------------------------------------
extern "C" void kernel_launch(void* const* d_in, const int* in_sizes, int n_in,
                              void* d_out, int out_size) {
    const float* X     = (const float*)d_in[0];
    const float* mask  = (const float*)d_in[1];
    const float* abias = (const float*)d_in[2];
    const float* Wq    = (const float*)d_in[3];
    const float* bq    = (const float*)d_in[4];
    const float* Wk    = (const float*)d_in[5];
    const float* bk    = (const float*)d_in[6];
    const float* Wv    = (const float*)d_in[7];
    const float* bv    = (const float*)d_in[8];
    const float* Wo    = (const float*)d_in[9];
    const float* bo    = (const float*)d_in[10];
    const float* beta  = (const float*)d_in[11];
    const float* bbias = (const float*)d_in[12];
    float* out = (float*)d_out;

    cudaFuncSetAttribute(attn_tc2_kernel,
                         cudaFuncAttributeMaxDynamicSharedMemorySize, ATT_SMEM);
    cudaFuncSetAttribute(qkv_gemm_pipe_kernel,
                         cudaFuncAttributeMaxDynamicSharedMemorySize, GEMM_SMEM);
    cudaFuncSetAttribute(oproj_gemm_pipe_kernel,
                         cudaFuncAttributeMaxDynamicSharedMemorySize, GEMM_SMEM);

    reset_flag_kernel<<<1, 32>>>();
    scan_mask_kernel<<<1024, 256>>>(mask, BSZ * SEQ * SEQ / 4);
    round_inputs_kernel<<<512, 256>>>(X, Wq, Wk, Wv, Wo);
    qkv_gemm_pipe_kernel<<<dim3(18, 32), 256, GEMM_SMEM>>>(bq, bk, bv);
    attn_tc2_kernel<<<dim3(SEQ / 128, BH), 128, ATT_SMEM>>>(mask, abias, beta, bbias);
    oproj_gemm_pipe_kernel<<<dim3(6, 32), 256, GEMM_SMEM>>>(bo, out);
}